// round 14
// baseline (speedup 1.0000x reference)
#include <cuda_runtime.h>

#define B_   8
#define C_   64
#define H_   128
#define W_   128
#define O_   16      // C / RED
#define G_   32      // total groups
#define GQ_  8       // groups per CTA (quarter)
#define GC_  2       // channels per group
#define KK_  9       // 3x3
#define KP_  10      // padded kernel stride (u64 units) for 16B alignment

typedef unsigned long long u64;

// scratch for t = PReLU(w1 @ x + b1): [B][O][H][W]
__device__ float t_scratch[B_ * O_ * H_ * W_];

__device__ __forceinline__ u64 pack2(float lo, float hi) {
    u64 r;
    asm("mov.b64 %0, {%1,%2};" : "=l"(r) : "f"(lo), "f"(hi));
    return r;
}
__device__ __forceinline__ void unpack2(u64 v, float& lo, float& hi) {
    asm("mov.b64 {%0,%1}, %2;" : "=f"(lo), "=f"(hi) : "l"(v));
}
// d = a*b + d, packed f32x2 (Blackwell FFMA2)
__device__ __forceinline__ void fma2(u64& d, u64 a, u64 b) {
    asm("fma.rn.f32x2 %0, %1, %2, %0;" : "+l"(d) : "l"(a), "l"(b));
}
__device__ __forceinline__ u64 add2(u64 a, u64 b) {
    u64 r;
    asm("add.rn.f32x2 %0, %1, %2;" : "=l"(r) : "l"(a), "l"(b));
    return r;
}
// explicit 128-bit shared load (forces LDS.128)
__device__ __forceinline__ ulonglong2 lds128(const ulonglong2* p) {
    ulonglong2 v;
    asm("ld.shared.v2.u64 {%0,%1}, [%2];"
        : "=l"(v.x), "=l"(v.y) : "l"(p));
    return v;
}
// non-binding L1 prefetch: no dest register, no fault on valid addrs
__device__ __forceinline__ void prefetch_l1(const void* p) {
    asm volatile("prefetch.global.L1 [%0];" :: "l"(p));
}

// ------- Kernel A: t = PReLU(w1 @ x + b1), 4 px/thread -------
__global__ void __launch_bounds__(64, 8) gen_t_kernel(
    const float* __restrict__ x,
    const float* __restrict__ w1,
    const float* __restrict__ b1,
    const float* __restrict__ pa)
{
    __shared__ float2 s_w1[C_ * O_];   // duplicated (s,s): 8 KB

    const int tid = threadIdx.x;
    for (int i = tid; i < C_ * O_; i += 64) {
        int c = i >> 4, o = i & 15;
        float v = w1[o * C_ + c];
        s_w1[i] = make_float2(v, v);
    }
    __syncthreads();

    const int b    = blockIdx.z;
    const int h    = blockIdx.y * 2 + (tid >> 5);   // 2 rows per CTA
    const int lane = tid & 31;
    const int w    = lane * 4;                      // 4 px: 2 pairs
    const float alpha = pa[0];

    const float* xc = x + (size_t)b * C_ * H_ * W_ + h * W_ + w;

    u64 tA[O_], tB[O_];
#pragma unroll
    for (int o = 0; o < O_; o++) {
        float bv = b1[o];
        tA[o] = pack2(bv, bv);
        tB[o] = tA[o];
    }

#pragma unroll 8
    for (int c = 0; c < C_; c++) {
        float4 xv = *reinterpret_cast<const float4*>(xc + c * (H_ * W_));
        u64 xpA = pack2(xv.x, xv.y);
        u64 xpB = pack2(xv.z, xv.w);
        const ulonglong2* wv = reinterpret_cast<const ulonglong2*>(&s_w1[c * O_]);
#pragma unroll
        for (int o2 = 0; o2 < 8; o2++) {
            ulonglong2 wpair = lds128(wv + o2);   // LDS.128, feeds 4 FFMA2
            fma2(tA[2 * o2 + 0], xpA, wpair.x);
            fma2(tB[2 * o2 + 0], xpB, wpair.x);
            fma2(tA[2 * o2 + 1], xpA, wpair.y);
            fma2(tB[2 * o2 + 1], xpB, wpair.y);
        }
    }

    // PReLU + store as packed pairs (STG.128)
    u64* tout = reinterpret_cast<u64*>(
        t_scratch + ((size_t)b * O_ * H_ + h) * W_ + w);
#pragma unroll
    for (int o = 0; o < O_; o++) {
        float a0, a1, a2, a3;
        unpack2(tA[o], a0, a1);
        unpack2(tB[o], a2, a3);
        a0 = (a0 >= 0.f) ? a0 : alpha * a0;
        a1 = (a1 >= 0.f) ? a1 : alpha * a1;
        a2 = (a2 >= 0.f) ? a2 : alpha * a2;
        a3 = (a3 >= 0.f) ? a3 : alpha * a3;
        ulonglong2 st;
        st.x = pack2(a0, a1);
        st.y = pack2(a2, a3);
        *reinterpret_cast<ulonglong2*>(tout + o * (H_ * W_ / 2)) = st;
    }
}

// ------- Kernel B: per-pixel kernels + 3x3 gather, 4 px/thread.
// Warp-staggered group order (breaks GEMV/gather phase lockstep) +
// L1 prefetch of next group's x rows (zero register cost). -------
__global__ void __launch_bounds__(128, 4) involution_apply_kernel(
    const float* __restrict__ x,
    const float* __restrict__ w2,
    const float* __restrict__ b2,
    float* __restrict__ out)
{
    // Duplicated-scalar (s,s) weight tables; quarter of the groups
    __shared__ float2 s_w2[GQ_ * O_ * KP_];  // [gl][o][kk pad10] : 10 KB
    __shared__ float2 s_b2[GQ_ * KP_];       // [gl][kk pad10]    : 640 B

    const int tid = threadIdx.y * 32 + threadIdx.x;
    const int g0  = blockIdx.x * GQ_;        // group-quarter base

    for (int i = tid; i < GQ_ * O_ * KK_; i += 128) {
        int kk = i % KK_;
        int rest = i / KK_;
        int o  = rest & 15;
        int gl = rest >> 4;
        float v = w2[((g0 + gl) * KK_ + kk) * O_ + o];
        s_w2[(gl * O_ + o) * KP_ + kk] = make_float2(v, v);
    }
    for (int i = tid; i < GQ_ * KP_; i += 128) {
        int gl = i / KP_, kk = i % KP_;
        float v = (kk < KK_) ? b2[(g0 + gl) * KK_ + kk] : 0.f;
        s_b2[i] = make_float2(v, v);
    }
    __syncthreads();

    const int b    = blockIdx.z;
    const int ty   = threadIdx.y;
    const int h    = blockIdx.y * 4 + ty;
    const int lane = threadIdx.x;            // warp spans one full row
    const int w    = lane * 4;               // 4 pixels: two FFMA2 pairs
    const int gofs = ty << 1;                // phase stagger: 0,2,4,6

    const float* xb = x + (size_t)b * C_ * H_ * W_;

    const bool hv0 = (h > 0);
    const bool hv2 = (h < H_ - 1);
    const bool lv  = (lane > 0);     // left halo valid (lane0 = image edge)
    const bool rv  = (lane < 31);    // right halo valid

    // Load t for both pixel pairs: one LDG.128 per o, pre-packed pairs
    u64 tv0[O_], tv1[O_];
    {
        const u64* tp = reinterpret_cast<const u64*>(
            t_scratch + ((size_t)b * O_ * H_ + h) * W_ + w);
#pragma unroll
        for (int o = 0; o < O_; o++) {
            ulonglong2 v = *reinterpret_cast<const ulonglong2*>(
                tp + o * (H_ * W_ / 2));
            tv0[o] = v.x;   // (t[w],   t[w+1])
            tv1[o] = v.y;   // (t[w+2], t[w+3])
        }
    }

    // prefetch first group's x rows into L1
    {
        const int gl = gofs;
#pragma unroll
        for (int cc = 0; cc < GC_; cc++) {
            const float* xr = xb + (size_t)((g0 + gl) * GC_ + cc) * (H_ * W_)
                              + h * W_ + w;
            prefetch_l1(xr);
            if (hv0) prefetch_l1(xr - W_);
            if (hv2) prefetch_l1(xr + W_);
        }
    }

    float* outp = out + (size_t)b * C_ * H_ * W_ + h * W_ + w;

#pragma unroll 1
    for (int gi = 0; gi < GQ_; gi++) {
        const int gl = (gi + gofs) & 7;      // staggered group order

        // prefetch NEXT group's x rows while this group's GEMV runs
        if (gi + 1 < GQ_) {
            const int gn = (gi + 1 + gofs) & 7;
#pragma unroll
            for (int cc = 0; cc < GC_; cc++) {
                const float* xr = xb
                    + (size_t)((g0 + gn) * GC_ + cc) * (H_ * W_) + h * W_ + w;
                prefetch_l1(xr);
                if (hv0) prefetch_l1(xr - W_);
                if (hv2) prefetch_l1(xr + W_);
            }
        }

        u64 wk0[KK_], wk1[KK_];
        {
            const u64* brow = reinterpret_cast<const u64*>(s_b2) + gl * KP_;
            const ulonglong2* brow2 = reinterpret_cast<const ulonglong2*>(brow);
#pragma unroll
            for (int kp = 0; kp < 4; kp++) {
                ulonglong2 v = lds128(brow2 + kp);
                wk0[2 * kp + 0] = v.x;  wk1[2 * kp + 0] = v.x;
                wk0[2 * kp + 1] = v.y;  wk1[2 * kp + 1] = v.y;
            }
            wk0[8] = brow[8];  wk1[8] = brow[8];
        }

        // weight GEMV: each LDS feeds 2 FFMA2 (one per pixel pair)
#pragma unroll
        for (int o = 0; o < O_; o++) {
            u64 t0 = tv0[o], t1 = tv1[o];
            const u64* wrow =
                reinterpret_cast<const u64*>(&s_w2[(gl * O_ + o) * KP_]);
            const ulonglong2* wrow2 = reinterpret_cast<const ulonglong2*>(wrow);
#pragma unroll
            for (int kp = 0; kp < 4; kp++) {
                ulonglong2 v = lds128(wrow2 + kp);
                fma2(wk0[2 * kp + 0], t0, v.x);
                fma2(wk1[2 * kp + 0], t1, v.x);
                fma2(wk0[2 * kp + 1], t0, v.y);
                fma2(wk1[2 * kp + 1], t1, v.y);
            }
            u64 v8 = wrow[8];
            fma2(wk0[8], t0, v8);
            fma2(wk1[8], t1, v8);
        }

        // 3x3 gather, 4 pixels; halo via warp shuffle (warp = full row)
#pragma unroll
        for (int cc = 0; cc < GC_; cc++) {
            const int c = (g0 + gl) * GC_ + cc;
            const float* xr = xb + (size_t)c * (H_ * W_) + h * W_ + w;
            u64 a0A = 0ULL, a0B = 0ULL;   // pair0: two dep chains
            u64 a1A = 0ULL, a1B = 0ULL;   // pair1
#pragma unroll
            for (int di = 0; di < 3; di++) {
                const bool hv = (di == 0) ? hv0 : ((di == 2) ? hv2 : true);
                const float* row = xr + (di - 1) * W_;
                ulonglong2 m = hv ? *reinterpret_cast<const ulonglong2*>(row)
                                  : make_ulonglong2(0ULL, 0ULL);
                float m0, m1, m2, m3;
                unpack2(m.x, m0, m1);
                unpack2(m.y, m2, m3);
                float L = __shfl_up_sync(0xffffffffu, m3, 1);
                float R = __shfl_down_sync(0xffffffffu, m0, 1);
                L = lv ? L : 0.f;
                R = rv ? R : 0.f;
                u64 pL  = pack2(L,  m0);
                u64 p12 = pack2(m1, m2);
                u64 p3R = pack2(m3, R);
                u64& acc0 = (di == 1) ? a0B : a0A;
                u64& acc1 = (di == 1) ? a1B : a1A;
                fma2(acc0, wk0[3 * di + 0], pL);
                fma2(acc0, wk0[3 * di + 1], m.x);
                fma2(acc0, wk0[3 * di + 2], p12);
                fma2(acc1, wk1[3 * di + 0], p12);
                fma2(acc1, wk1[3 * di + 1], m.y);
                fma2(acc1, wk1[3 * di + 2], p3R);
            }
            ulonglong2 res;
            res.x = add2(a0A, a0B);
            res.y = add2(a1A, a1B);
            *reinterpret_cast<ulonglong2*>(outp + (size_t)c * (H_ * W_)) = res;
        }
    }
}

extern "C" void kernel_launch(void* const* d_in, const int* in_sizes, int n_in,
                              void* d_out, int out_size)
{
    (void)in_sizes; (void)n_in; (void)out_size;
    const float* x  = (const float*)d_in[0];
    const float* w1 = (const float*)d_in[1];
    const float* b1 = (const float*)d_in[2];
    const float* pa = (const float*)d_in[3];
    const float* w2 = (const float*)d_in[4];
    const float* b2 = (const float*)d_in[5];
    float* out = (float*)d_out;

    // Kernel A: 512 CTAs, 4 px/thread
    dim3 blockA(64, 1, 1);
    dim3 gridA(1, H_ / 2, B_);
    gen_t_kernel<<<gridA, blockA>>>(x, w1, b1, pa);

    // Kernel B: 1024 CTAs, 4-way group split, 4 px/thread
    dim3 blockB(32, 4, 1);
    dim3 gridB(4, H_ / 4, B_);
    involution_apply_kernel<<<gridB, blockB>>>(x, w2, b2, out);
}

// round 16
// speedup vs baseline: 1.0780x; 1.0780x over previous
#include <cuda_runtime.h>

#define B_   8
#define C_   64
#define H_   128
#define W_   128
#define O_   16      // C / RED
#define G_   32      // total groups
#define GQ_  8       // groups per CTA (quarter)
#define GC_  2       // channels per group
#define KK_  9       // 3x3
#define KP_  10      // padded kernel stride (u64 units) for 16B alignment

typedef unsigned long long u64;

// scratch for t = PReLU(w1 @ x + b1): [B][O][H][W]
__device__ float t_scratch[B_ * O_ * H_ * W_];

__device__ __forceinline__ u64 pack2(float lo, float hi) {
    u64 r;
    asm("mov.b64 %0, {%1,%2};" : "=l"(r) : "f"(lo), "f"(hi));
    return r;
}
__device__ __forceinline__ void unpack2(u64 v, float& lo, float& hi) {
    asm("mov.b64 {%0,%1}, %2;" : "=f"(lo), "=f"(hi) : "l"(v));
}
// d = a*b + d, packed f32x2 (Blackwell FFMA2)
__device__ __forceinline__ void fma2(u64& d, u64 a, u64 b) {
    asm("fma.rn.f32x2 %0, %1, %2, %0;" : "+l"(d) : "l"(a), "l"(b));
}
__device__ __forceinline__ u64 add2(u64 a, u64 b) {
    u64 r;
    asm("add.rn.f32x2 %0, %1, %2;" : "=l"(r) : "l"(a), "l"(b));
    return r;
}
// explicit 128-bit shared load (forces LDS.128)
__device__ __forceinline__ ulonglong2 lds128(const ulonglong2* p) {
    ulonglong2 v;
    asm("ld.shared.v2.u64 {%0,%1}, [%2];"
        : "=l"(v.x), "=l"(v.y) : "l"(p));
    return v;
}

// ------- Kernel A: t = PReLU(w1 @ x + b1), 4 px/thread -------
__global__ void __launch_bounds__(64, 8) gen_t_kernel(
    const float* __restrict__ x,
    const float* __restrict__ w1,
    const float* __restrict__ b1,
    const float* __restrict__ pa)
{
    __shared__ float2 s_w1[C_ * O_];   // duplicated (s,s): 8 KB

    const int tid = threadIdx.x;
    for (int i = tid; i < C_ * O_; i += 64) {
        int c = i >> 4, o = i & 15;
        float v = w1[o * C_ + c];
        s_w1[i] = make_float2(v, v);
    }
    __syncthreads();

    const int b    = blockIdx.z;
    const int h    = blockIdx.y * 2 + (tid >> 5);   // 2 rows per CTA
    const int lane = tid & 31;
    const int w    = lane * 4;                      // 4 px: 2 pairs
    const float alpha = pa[0];

    const float* xc = x + (size_t)b * C_ * H_ * W_ + h * W_ + w;

    u64 tA[O_], tB[O_];
#pragma unroll
    for (int o = 0; o < O_; o++) {
        float bv = b1[o];
        tA[o] = pack2(bv, bv);
        tB[o] = tA[o];
    }

#pragma unroll 4
    for (int c = 0; c < C_; c++) {
        float4 xv = *reinterpret_cast<const float4*>(xc + c * (H_ * W_));
        u64 xpA = pack2(xv.x, xv.y);
        u64 xpB = pack2(xv.z, xv.w);
        const ulonglong2* wv = reinterpret_cast<const ulonglong2*>(&s_w1[c * O_]);
#pragma unroll
        for (int o2 = 0; o2 < 8; o2++) {
            ulonglong2 wpair = lds128(wv + o2);   // LDS.128, feeds 4 FFMA2
            fma2(tA[2 * o2 + 0], xpA, wpair.x);
            fma2(tB[2 * o2 + 0], xpB, wpair.x);
            fma2(tA[2 * o2 + 1], xpA, wpair.y);
            fma2(tB[2 * o2 + 1], xpB, wpair.y);
        }
    }

    // PReLU + store as packed pairs (STG.128)
    u64* tout = reinterpret_cast<u64*>(
        t_scratch + ((size_t)b * O_ * H_ + h) * W_ + w);
#pragma unroll
    for (int o = 0; o < O_; o++) {
        float a0, a1, a2, a3;
        unpack2(tA[o], a0, a1);
        unpack2(tB[o], a2, a3);
        a0 = (a0 >= 0.f) ? a0 : alpha * a0;
        a1 = (a1 >= 0.f) ? a1 : alpha * a1;
        a2 = (a2 >= 0.f) ? a2 : alpha * a2;
        a3 = (a3 >= 0.f) ? a3 : alpha * a3;
        ulonglong2 st;
        st.x = pack2(a0, a1);
        st.y = pack2(a2, a3);
        *reinterpret_cast<ulonglong2*>(tout + o * (H_ * W_ / 2)) = st;
    }
}

// ------- Kernel B: per-pixel kernels + 3x3 gather, 4 px/thread.
// R13 structure + warp-staggered group order ONLY (no prefetch):
// breaks GEMV/gather phase lockstep at ~1 instr/group cost. -------
__global__ void __launch_bounds__(128, 4) involution_apply_kernel(
    const float* __restrict__ x,
    const float* __restrict__ w2,
    const float* __restrict__ b2,
    float* __restrict__ out)
{
    // Duplicated-scalar (s,s) weight tables; quarter of the groups
    __shared__ float2 s_w2[GQ_ * O_ * KP_];  // [gl][o][kk pad10] : 10 KB
    __shared__ float2 s_b2[GQ_ * KP_];       // [gl][kk pad10]    : 640 B

    const int tid = threadIdx.y * 32 + threadIdx.x;
    const int g0  = blockIdx.x * GQ_;        // group-quarter base

    for (int i = tid; i < GQ_ * O_ * KK_; i += 128) {
        int kk = i % KK_;
        int rest = i / KK_;
        int o  = rest & 15;
        int gl = rest >> 4;
        float v = w2[((g0 + gl) * KK_ + kk) * O_ + o];
        s_w2[(gl * O_ + o) * KP_ + kk] = make_float2(v, v);
    }
    for (int i = tid; i < GQ_ * KP_; i += 128) {
        int gl = i / KP_, kk = i % KP_;
        float v = (kk < KK_) ? b2[(g0 + gl) * KK_ + kk] : 0.f;
        s_b2[i] = make_float2(v, v);
    }
    __syncthreads();

    const int b    = blockIdx.z;
    const int ty   = threadIdx.y;
    const int h    = blockIdx.y * 4 + ty;
    const int lane = threadIdx.x;            // warp spans one full row
    const int w    = lane * 4;               // 4 pixels: two FFMA2 pairs
    const int gofs = ty << 1;                // phase stagger: 0,2,4,6

    const float* xb = x + (size_t)b * C_ * H_ * W_;

    // Load t for both pixel pairs: one LDG.128 per o, pre-packed pairs
    u64 tv0[O_], tv1[O_];
    {
        const u64* tp = reinterpret_cast<const u64*>(
            t_scratch + ((size_t)b * O_ * H_ + h) * W_ + w);
#pragma unroll
        for (int o = 0; o < O_; o++) {
            ulonglong2 v = *reinterpret_cast<const ulonglong2*>(
                tp + o * (H_ * W_ / 2));
            tv0[o] = v.x;   // (t[w],   t[w+1])
            tv1[o] = v.y;   // (t[w+2], t[w+3])
        }
    }

    const bool hv0 = (h > 0);
    const bool hv2 = (h < H_ - 1);
    const bool lv  = (lane > 0);     // left halo valid (lane0 = image edge)
    const bool rv  = (lane < 31);    // right halo valid

    float* outp = out + (size_t)b * C_ * H_ * W_ + h * W_ + w;

#pragma unroll 1
    for (int gi = 0; gi < GQ_; gi++) {
        const int gl = (gi + gofs) & 7;      // staggered group order

        u64 wk0[KK_], wk1[KK_];
        {
            const u64* brow = reinterpret_cast<const u64*>(s_b2) + gl * KP_;
            const ulonglong2* brow2 = reinterpret_cast<const ulonglong2*>(brow);
#pragma unroll
            for (int kp = 0; kp < 4; kp++) {
                ulonglong2 v = lds128(brow2 + kp);
                wk0[2 * kp + 0] = v.x;  wk1[2 * kp + 0] = v.x;
                wk0[2 * kp + 1] = v.y;  wk1[2 * kp + 1] = v.y;
            }
            wk0[8] = brow[8];  wk1[8] = brow[8];
        }

        // weight GEMV: each LDS feeds 2 FFMA2 (one per pixel pair)
#pragma unroll
        for (int o = 0; o < O_; o++) {
            u64 t0 = tv0[o], t1 = tv1[o];
            const u64* wrow =
                reinterpret_cast<const u64*>(&s_w2[(gl * O_ + o) * KP_]);
            const ulonglong2* wrow2 = reinterpret_cast<const ulonglong2*>(wrow);
#pragma unroll
            for (int kp = 0; kp < 4; kp++) {
                ulonglong2 v = lds128(wrow2 + kp);
                fma2(wk0[2 * kp + 0], t0, v.x);
                fma2(wk1[2 * kp + 0], t1, v.x);
                fma2(wk0[2 * kp + 1], t0, v.y);
                fma2(wk1[2 * kp + 1], t1, v.y);
            }
            u64 v8 = wrow[8];
            fma2(wk0[8], t0, v8);
            fma2(wk1[8], t1, v8);
        }

        // 3x3 gather, 4 pixels; halo via warp shuffle (warp = full row)
#pragma unroll
        for (int cc = 0; cc < GC_; cc++) {
            const int c = (g0 + gl) * GC_ + cc;
            const float* xr = xb + (size_t)c * (H_ * W_) + h * W_ + w;
            u64 a0A = 0ULL, a0B = 0ULL;   // pair0: two dep chains
            u64 a1A = 0ULL, a1B = 0ULL;   // pair1
#pragma unroll
            for (int di = 0; di < 3; di++) {
                const bool hv = (di == 0) ? hv0 : ((di == 2) ? hv2 : true);
                const float* row = xr + (di - 1) * W_;
                ulonglong2 m = hv ? *reinterpret_cast<const ulonglong2*>(row)
                                  : make_ulonglong2(0ULL, 0ULL);
                float m0, m1, m2, m3;
                unpack2(m.x, m0, m1);
                unpack2(m.y, m2, m3);
                float L = __shfl_up_sync(0xffffffffu, m3, 1);
                float R = __shfl_down_sync(0xffffffffu, m0, 1);
                L = lv ? L : 0.f;
                R = rv ? R : 0.f;
                u64 pL  = pack2(L,  m0);
                u64 p12 = pack2(m1, m2);
                u64 p3R = pack2(m3, R);
                u64& acc0 = (di == 1) ? a0B : a0A;
                u64& acc1 = (di == 1) ? a1B : a1A;
                fma2(acc0, wk0[3 * di + 0], pL);
                fma2(acc0, wk0[3 * di + 1], m.x);
                fma2(acc0, wk0[3 * di + 2], p12);
                fma2(acc1, wk1[3 * di + 0], p12);
                fma2(acc1, wk1[3 * di + 1], m.y);
                fma2(acc1, wk1[3 * di + 2], p3R);
            }
            ulonglong2 res;
            res.x = add2(a0A, a0B);
            res.y = add2(a1A, a1B);
            *reinterpret_cast<ulonglong2*>(outp + (size_t)c * (H_ * W_)) = res;
        }
    }
}

extern "C" void kernel_launch(void* const* d_in, const int* in_sizes, int n_in,
                              void* d_out, int out_size)
{
    (void)in_sizes; (void)n_in; (void)out_size;
    const float* x  = (const float*)d_in[0];
    const float* w1 = (const float*)d_in[1];
    const float* b1 = (const float*)d_in[2];
    const float* pa = (const float*)d_in[3];
    const float* w2 = (const float*)d_in[4];
    const float* b2 = (const float*)d_in[5];
    float* out = (float*)d_out;

    // Kernel A: 512 CTAs, 4 px/thread
    dim3 blockA(64, 1, 1);
    dim3 gridA(1, H_ / 2, B_);
    gen_t_kernel<<<gridA, blockA>>>(x, w1, b1, pa);

    // Kernel B: 1024 CTAs, 4-way group split, 4 px/thread
    dim3 blockB(32, 4, 1);
    dim3 gridB(4, H_ / 4, B_);
    involution_apply_kernel<<<gridB, blockB>>>(x, w2, b2, out);
}

// round 17
// speedup vs baseline: 1.1635x; 1.0793x over previous
#include <cuda_runtime.h>

#define B_   8
#define C_   64
#define H_   128
#define W_   128
#define O_   16      // C / RED
#define G_   32      // total groups
#define GQ_  8       // groups per CTA (quarter)
#define GC_  2       // channels per group
#define KK_  9       // 3x3
#define KP_  10      // padded kernel stride (u64 units) for 16B alignment

typedef unsigned long long u64;

// scratch for t = PReLU(w1 @ x + b1): [B][O][H][W]
__device__ float t_scratch[B_ * O_ * H_ * W_];

__device__ __forceinline__ u64 pack2(float lo, float hi) {
    u64 r;
    asm("mov.b64 %0, {%1,%2};" : "=l"(r) : "f"(lo), "f"(hi));
    return r;
}
__device__ __forceinline__ void unpack2(u64 v, float& lo, float& hi) {
    asm("mov.b64 {%0,%1}, %2;" : "=f"(lo), "=f"(hi) : "l"(v));
}
// d = a*b + d, packed f32x2 (Blackwell FFMA2)
__device__ __forceinline__ void fma2(u64& d, u64 a, u64 b) {
    asm("fma.rn.f32x2 %0, %1, %2, %0;" : "+l"(d) : "l"(a), "l"(b));
}
// d = a*b + c (separate addend — used to fuse bias into first GEMV step)
__device__ __forceinline__ void fma2_init(u64& d, u64 a, u64 b, u64 c) {
    asm("fma.rn.f32x2 %0, %1, %2, %3;" : "=l"(d) : "l"(a), "l"(b), "l"(c));
}
// explicit 128-bit shared load (forces LDS.128)
__device__ __forceinline__ ulonglong2 lds128(const ulonglong2* p) {
    ulonglong2 v;
    asm("ld.shared.v2.u64 {%0,%1}, [%2];"
        : "=l"(v.x), "=l"(v.y) : "l"(p));
    return v;
}

// ------- Kernel A: t = PReLU(w1 @ x + b1), 4 px/thread -------
__global__ void __launch_bounds__(64, 8) gen_t_kernel(
    const float* __restrict__ x,
    const float* __restrict__ w1,
    const float* __restrict__ b1,
    const float* __restrict__ pa)
{
    __shared__ float2 s_w1[C_ * O_];   // duplicated (s,s): 8 KB

    const int tid = threadIdx.x;
    for (int i = tid; i < C_ * O_; i += 64) {
        int c = i >> 4, o = i & 15;
        float v = w1[o * C_ + c];
        s_w1[i] = make_float2(v, v);
    }
    __syncthreads();

    const int b    = blockIdx.z;
    const int h    = blockIdx.y * 2 + (tid >> 5);   // 2 rows per CTA
    const int lane = tid & 31;
    const int w    = lane * 4;                      // 4 px: 2 pairs
    const float alpha = pa[0];

    const float* xc = x + (size_t)b * C_ * H_ * W_ + h * W_ + w;

    u64 tA[O_], tB[O_];
#pragma unroll
    for (int o = 0; o < O_; o++) {
        float bv = b1[o];
        tA[o] = pack2(bv, bv);
        tB[o] = tA[o];
    }

#pragma unroll 4
    for (int c = 0; c < C_; c++) {
        float4 xv = *reinterpret_cast<const float4*>(xc + c * (H_ * W_));
        u64 xpA = pack2(xv.x, xv.y);
        u64 xpB = pack2(xv.z, xv.w);
        const ulonglong2* wv = reinterpret_cast<const ulonglong2*>(&s_w1[c * O_]);
#pragma unroll
        for (int o2 = 0; o2 < 8; o2++) {
            ulonglong2 wpair = lds128(wv + o2);   // LDS.128, feeds 4 FFMA2
            fma2(tA[2 * o2 + 0], xpA, wpair.x);
            fma2(tB[2 * o2 + 0], xpB, wpair.x);
            fma2(tA[2 * o2 + 1], xpA, wpair.y);
            fma2(tB[2 * o2 + 1], xpB, wpair.y);
        }
    }

    // PReLU + store as packed pairs (STG.128)
    u64* tout = reinterpret_cast<u64*>(
        t_scratch + ((size_t)b * O_ * H_ + h) * W_ + w);
#pragma unroll
    for (int o = 0; o < O_; o++) {
        float a0, a1, a2, a3;
        unpack2(tA[o], a0, a1);
        unpack2(tB[o], a2, a3);
        a0 = (a0 >= 0.f) ? a0 : alpha * a0;
        a1 = (a1 >= 0.f) ? a1 : alpha * a1;
        a2 = (a2 >= 0.f) ? a2 : alpha * a2;
        a3 = (a3 >= 0.f) ? a3 : alpha * a3;
        ulonglong2 st;
        st.x = pack2(a0, a1);
        st.y = pack2(a2, a3);
        *reinterpret_cast<ulonglong2*>(tout + o * (H_ * W_ / 2)) = st;
    }
}

// ------- Kernel B (R13 structure): per-pixel kernels + 3x3 gather,
// 4 px/thread; bias fused into o=0 GEMV step (no wk-init block). -------
__global__ void __launch_bounds__(128, 4) involution_apply_kernel(
    const float* __restrict__ x,
    const float* __restrict__ w2,
    const float* __restrict__ b2,
    float* __restrict__ out)
{
    // Duplicated-scalar (s,s) weight tables; quarter of the groups
    __shared__ float2 s_w2[GQ_ * O_ * KP_];  // [gl][o][kk pad10] : 10 KB
    __shared__ float2 s_b2[GQ_ * KP_];       // [gl][kk pad10]    : 640 B

    const int tid = threadIdx.y * 32 + threadIdx.x;
    const int g0  = blockIdx.x * GQ_;        // group-quarter base

    for (int i = tid; i < GQ_ * O_ * KK_; i += 128) {
        int kk = i % KK_;
        int rest = i / KK_;
        int o  = rest & 15;
        int gl = rest >> 4;
        float v = w2[((g0 + gl) * KK_ + kk) * O_ + o];
        s_w2[(gl * O_ + o) * KP_ + kk] = make_float2(v, v);
    }
    for (int i = tid; i < GQ_ * KP_; i += 128) {
        int gl = i / KP_, kk = i % KP_;
        float v = (kk < KK_) ? b2[(g0 + gl) * KK_ + kk] : 0.f;
        s_b2[i] = make_float2(v, v);
    }
    __syncthreads();

    const int b    = blockIdx.z;
    const int h    = blockIdx.y * 4 + threadIdx.y;
    const int lane = threadIdx.x;            // warp spans one full row
    const int w    = lane * 4;               // 4 pixels: two FFMA2 pairs

    const float* xb = x + (size_t)b * C_ * H_ * W_;

    // Load t for both pixel pairs: one LDG.128 per o, pre-packed pairs
    u64 tv0[O_], tv1[O_];
    {
        const u64* tp = reinterpret_cast<const u64*>(
            t_scratch + ((size_t)b * O_ * H_ + h) * W_ + w);
#pragma unroll
        for (int o = 0; o < O_; o++) {
            ulonglong2 v = *reinterpret_cast<const ulonglong2*>(
                tp + o * (H_ * W_ / 2));
            tv0[o] = v.x;   // (t[w],   t[w+1])
            tv1[o] = v.y;   // (t[w+2], t[w+3])
        }
    }

    const bool hv0 = (h > 0);
    const bool hv2 = (h < H_ - 1);
    const bool lv  = (lane > 0);     // left halo valid (lane0 = image edge)
    const bool rv  = (lane < 31);    // right halo valid

    float* outp = out + (size_t)b * C_ * H_ * W_ + h * W_ + w;

#pragma unroll 1
    for (int gl = 0; gl < GQ_; gl++) {
        u64 wk0[KK_], wk1[KK_];

        // o = 0: wk = t[0]*w[0][kk] + bias[kk]  (bias fused as addend)
        {
            u64 t0 = tv0[0], t1 = tv1[0];
            const u64* wrow = reinterpret_cast<const u64*>(&s_w2[(gl * O_) * KP_]);
            const ulonglong2* wrow2 = reinterpret_cast<const ulonglong2*>(wrow);
            const u64* brow = reinterpret_cast<const u64*>(s_b2) + gl * KP_;
            const ulonglong2* brow2 = reinterpret_cast<const ulonglong2*>(brow);
#pragma unroll
            for (int kp = 0; kp < 4; kp++) {
                ulonglong2 v  = lds128(wrow2 + kp);
                ulonglong2 bb = lds128(brow2 + kp);
                fma2_init(wk0[2 * kp + 0], t0, v.x, bb.x);
                fma2_init(wk1[2 * kp + 0], t1, v.x, bb.x);
                fma2_init(wk0[2 * kp + 1], t0, v.y, bb.y);
                fma2_init(wk1[2 * kp + 1], t1, v.y, bb.y);
            }
            u64 v8 = wrow[8], b8 = brow[8];
            fma2_init(wk0[8], t0, v8, b8);
            fma2_init(wk1[8], t1, v8, b8);
        }

        // o = 1..15: accumulate
#pragma unroll
        for (int o = 1; o < O_; o++) {
            u64 t0 = tv0[o], t1 = tv1[o];
            const u64* wrow =
                reinterpret_cast<const u64*>(&s_w2[(gl * O_ + o) * KP_]);
            const ulonglong2* wrow2 = reinterpret_cast<const ulonglong2*>(wrow);
#pragma unroll
            for (int kp = 0; kp < 4; kp++) {
                ulonglong2 v = lds128(wrow2 + kp);
                fma2(wk0[2 * kp + 0], t0, v.x);
                fma2(wk1[2 * kp + 0], t1, v.x);
                fma2(wk0[2 * kp + 1], t0, v.y);
                fma2(wk1[2 * kp + 1], t1, v.y);
            }
            u64 v8 = wrow[8];
            fma2(wk0[8], t0, v8);
            fma2(wk1[8], t1, v8);
        }

        // 3x3 gather, 4 pixels; halo via warp shuffle (warp = full row)
#pragma unroll
        for (int cc = 0; cc < GC_; cc++) {
            const int c = (g0 + gl) * GC_ + cc;
            const float* xr = xb + (size_t)c * (H_ * W_) + h * W_ + w;
            u64 acc0 = 0ULL, acc1 = 0ULL;
#pragma unroll
            for (int di = 0; di < 3; di++) {
                const bool hv = (di == 0) ? hv0 : ((di == 2) ? hv2 : true);
                const float* row = xr + (di - 1) * W_;
                ulonglong2 m = hv ? *reinterpret_cast<const ulonglong2*>(row)
                                  : make_ulonglong2(0ULL, 0ULL);
                float m0, m1, m2, m3;
                unpack2(m.x, m0, m1);
                unpack2(m.y, m2, m3);
                float L = __shfl_up_sync(0xffffffffu, m3, 1);
                float R = __shfl_down_sync(0xffffffffu, m0, 1);
                L = lv ? L : 0.f;
                R = rv ? R : 0.f;
                u64 pL  = pack2(L,  m0);
                u64 p12 = pack2(m1, m2);
                u64 p3R = pack2(m3, R);
                fma2(acc0, wk0[3 * di + 0], pL);
                fma2(acc0, wk0[3 * di + 1], m.x);
                fma2(acc0, wk0[3 * di + 2], p12);
                fma2(acc1, wk1[3 * di + 0], p12);
                fma2(acc1, wk1[3 * di + 1], m.y);
                fma2(acc1, wk1[3 * di + 2], p3R);
            }
            ulonglong2 res;
            res.x = acc0;
            res.y = acc1;
            *reinterpret_cast<ulonglong2*>(outp + (size_t)c * (H_ * W_)) = res;
        }
    }
}

extern "C" void kernel_launch(void* const* d_in, const int* in_sizes, int n_in,
                              void* d_out, int out_size)
{
    (void)in_sizes; (void)n_in; (void)out_size;
    const float* x  = (const float*)d_in[0];
    const float* w1 = (const float*)d_in[1];
    const float* b1 = (const float*)d_in[2];
    const float* pa = (const float*)d_in[3];
    const float* w2 = (const float*)d_in[4];
    const float* b2 = (const float*)d_in[5];
    float* out = (float*)d_out;

    // Kernel A: 512 CTAs, 4 px/thread
    dim3 blockA(64, 1, 1);
    dim3 gridA(1, H_ / 2, B_);
    gen_t_kernel<<<gridA, blockA>>>(x, w1, b1, pa);

    // Kernel B: 1024 CTAs, 4-way group split, 4 px/thread
    dim3 blockB(32, 4, 1);
    dim3 gridB(4, H_ / 4, B_);
    involution_apply_kernel<<<gridB, blockB>>>(x, w2, b2, out);
}